// round 1
// baseline (speedup 1.0000x reference)
#include <cuda_runtime.h>
#include <cuda_bf16.h>
#include <math.h>

// Problem constants
#define B_ 4
#define T_ 1024
#define E_ 1024
#define H_ 8
#define DH_ 128
#define KV_ 2304
#define CML_ 256
#define MEML_ 1024
#define TOTMEM_ 1280
#define SCALE_ 0.08838834764831845f

// Scratch (device globals — allocation-free rule)
__device__ float g_q[B_ * T_ * E_];
__device__ float g_k[B_ * KV_ * E_];
__device__ float g_v[B_ * KV_ * E_];
__device__ float g_attn[B_ * T_ * E_];
__device__ float g_pos[(size_t)B_ * H_ * T_ * KV_];   // scaled pos_dots, pre-shift

#define MODE_Q 0
#define MODE_KV 1
#define MODE_POS 2
#define MODE_OUT 3
#define MODE_CMEM 4

// ---------------------------------------------------------------------------
// Generic tiled fp32 SGEMM: 128x128x16 block tile, 8x8 per thread, 256 threads
// ---------------------------------------------------------------------------
template <int MODE>
__launch_bounds__(256)
__global__ void sgemm_kernel(const float* __restrict__ A0,
                             const float* __restrict__ A1,
                             const float* __restrict__ A2,
                             const float* __restrict__ Bm,
                             const float* __restrict__ bias,
                             float* __restrict__ Cout)
{
    constexpr int BM = 128, BN = 128, BK = 16;
    constexpr int K = (MODE == MODE_POS) ? 128 : (MODE == MODE_CMEM ? 4096 : 1024);
    constexpr int N = (MODE == MODE_KV) ? 2048 : (MODE == MODE_POS ? 2304 : 1024);

    __shared__ float As[BK][BM + 4];
    __shared__ float Bs[BK][BN + 4];

    const int tid = threadIdx.x;
    const int tx = tid & 15;
    const int ty = tid >> 4;
    const int m0 = blockIdx.y * BM;
    const int n0 = blockIdx.x * BN;

    // ---- per-thread A row pointer (gather per mode) ----
    const int arow = tid >> 1;        // 0..127
    const int ak = (tid & 1) * 8;     // 0 or 8
    const int gm = m0 + arow;
    const float* aRow;
    if constexpr (MODE == MODE_Q) {
        aRow = A0 + (size_t)gm * 1024;
    } else if constexpr (MODE == MODE_KV) {
        int b = gm / KV_;
        int j = gm - b * KV_;
        if (j < CML_)              aRow = A2 + (size_t)(b * CML_ + j) * 1024;
        else if (j < CML_ + MEML_) aRow = A1 + (size_t)(b * MEML_ + (j - CML_)) * 1024;
        else                       aRow = A0 + (size_t)(b * T_ + (j - CML_ - MEML_)) * 1024;
    } else if constexpr (MODE == MODE_POS) {
        int bh = blockIdx.z;
        int b = bh >> 3, h = bh & 7;
        aRow = g_q + (size_t)(b * T_ + gm) * 1024 + h * 128;
    } else if constexpr (MODE == MODE_OUT) {
        aRow = g_attn + (size_t)gm * 1024;
    } else { // CMEM: A[m][k] with k = d*4+r -> mem[m*4096 + r*1024 + d]
        aRow = A1 + (size_t)gm * 4096;
    }

    // ---- B base pointer ----
    const float* Bbase = Bm;
    if constexpr (MODE == MODE_POS) {
        int h = blockIdx.z & 7;
        Bbase = Bm + (size_t)h * KV_ * 128;   // pe[h] : (KV_, 128) row-major (NxK)
    }

    const int brow = tid >> 5;          // KxN loader: 0..7
    const int bcol = (tid & 31) * 4;
    const int bn = tid >> 1;            // NxK loader: 0..127
    const int bk = (tid & 1) * 8;

    float acc[8][8];
#pragma unroll
    for (int i = 0; i < 8; i++)
#pragma unroll
        for (int j = 0; j < 8; j++) acc[i][j] = 0.f;

    for (int k0 = 0; k0 < K; k0 += BK) {
        // Load A tile (transposed into As[k][m])
        if constexpr (MODE == MODE_CMEM) {
            int kb = (k0 + ak) >> 2;
#pragma unroll
            for (int j = 0; j < 8; j++)
                As[ak + j][arow] = aRow[(j & 3) * 1024 + kb + (j >> 2)];
        } else {
            float4 v0 = *(const float4*)(aRow + k0 + ak);
            float4 v1 = *(const float4*)(aRow + k0 + ak + 4);
            As[ak + 0][arow] = v0.x; As[ak + 1][arow] = v0.y;
            As[ak + 2][arow] = v0.z; As[ak + 3][arow] = v0.w;
            As[ak + 4][arow] = v1.x; As[ak + 5][arow] = v1.y;
            As[ak + 6][arow] = v1.z; As[ak + 7][arow] = v1.w;
        }
        // Load B tile
        if constexpr (MODE == MODE_POS || MODE == MODE_CMEM) {
            // B given as (N, K) row-major -> Bs[k][n]
            const float* p = Bbase + (size_t)(n0 + bn) * K + k0 + bk;
            float4 v0 = *(const float4*)(p);
            float4 v1 = *(const float4*)(p + 4);
            Bs[bk + 0][bn] = v0.x; Bs[bk + 1][bn] = v0.y;
            Bs[bk + 2][bn] = v0.z; Bs[bk + 3][bn] = v0.w;
            Bs[bk + 4][bn] = v1.x; Bs[bk + 5][bn] = v1.y;
            Bs[bk + 6][bn] = v1.z; Bs[bk + 7][bn] = v1.w;
        } else {
            // B given as (K, N) row-major
            float4 v0 = *(const float4*)(Bbase + (size_t)(k0 + brow) * N + n0 + bcol);
            float4 v1 = *(const float4*)(Bbase + (size_t)(k0 + brow + 8) * N + n0 + bcol);
            *(float4*)&Bs[brow][bcol] = v0;
            *(float4*)&Bs[brow + 8][bcol] = v1;
        }
        __syncthreads();

#pragma unroll
        for (int kk = 0; kk < BK; kk++) {
            float a[8], bb[8];
#pragma unroll
            for (int i = 0; i < 8; i++) a[i] = As[kk][ty + 16 * i];
#pragma unroll
            for (int j = 0; j < 8; j++) bb[j] = Bs[kk][tx + 16 * j];
#pragma unroll
            for (int i = 0; i < 8; i++)
#pragma unroll
                for (int j = 0; j < 8; j++)
                    acc[i][j] = fmaf(a[i], bb[j], acc[i][j]);
        }
        __syncthreads();
    }

    // ---- store C ----
#pragma unroll
    for (int i = 0; i < 8; i++) {
        int row = m0 + ty + 16 * i;
#pragma unroll
        for (int j = 0; j < 8; j++) {
            int col = n0 + tx + 16 * j;
            float v = acc[i][j];
            if constexpr (MODE == MODE_Q) {
                g_q[(size_t)row * 1024 + col] = v;
            } else if constexpr (MODE == MODE_KV) {
                if (col < 1024) g_k[(size_t)row * 1024 + col] = v;
                else            g_v[(size_t)row * 1024 + col - 1024] = v;
            } else if constexpr (MODE == MODE_POS) {
                int bh = blockIdx.z;
                g_pos[((size_t)bh * T_ + row) * KV_ + col] = v * SCALE_;
            } else { // OUT, CMEM
                Cout[(size_t)row * 1024 + col] = v + bias[col];
            }
        }
    }
}

// ---------------------------------------------------------------------------
// Flash-style attention: block = 64 queries for one (b,h); 64-wide KV tiles.
// score = Qscaled·K + g_pos[bh,q,m-q+1023] inside the band m<=q+1280, else -inf
// ---------------------------------------------------------------------------
#define ATTN_SMEM_BYTES ((64 * 132 * 2 + 64 * 65) * 4)

__launch_bounds__(256, 2)
__global__ void attn_kernel()
{
    extern __shared__ float sm[];
    float* Qs  = sm;                // 64 x 132
    float* KVs = sm + 64 * 132;     // 64 x 132 (K, then reused for V)
    float* Ps  = sm + 2 * 64 * 132; // 64 x 65

    const int tid = threadIdx.x;
    const int tx = tid & 15;
    const int ty = tid >> 4;
    const int qx = (int)gridDim.x - 1 - (int)blockIdx.x;  // heavy tiles first
    const int q0 = qx * 64;
    const int bh = blockIdx.y;
    const int b = bh >> 3, h = bh & 7;

    // Load Q tile, pre-scaled
    {
        int r = tid >> 5;
        int c4 = (tid & 31) * 4;
#pragma unroll
        for (int it = 0; it < 8; it++) {
            int row = r + it * 8;
            float4 v = *(const float4*)(g_q + (size_t)(b * T_ + q0 + row) * 1024 + h * 128 + c4);
            v.x *= SCALE_; v.y *= SCALE_; v.z *= SCALE_; v.w *= SCALE_;
            *(float4*)&Qs[row * 132 + c4] = v;
        }
    }

    float m_run[4], l_run[4], o[4][8];
#pragma unroll
    for (int i = 0; i < 4; i++) {
        m_run[i] = -INFINITY;
        l_run[i] = 0.f;
#pragma unroll
        for (int c = 0; c < 8; c++) o[i][c] = 0.f;
    }

    const int n_tiles = min(KV_ / 64, qx + 21);
    const float* pos_base = g_pos + (size_t)bh * T_ * KV_;

    for (int t = 0; t < n_tiles; t++) {
        const int m0 = t * 64;
        __syncthreads();  // Qs ready (first iter) / prior V consumed
        // Load K tile
        {
            int r = tid >> 5;
            int c4 = (tid & 31) * 4;
#pragma unroll
            for (int it = 0; it < 8; it++) {
                int row = r + it * 8;
                float4 v = *(const float4*)(g_k + (size_t)(b * KV_ + m0 + row) * 1024 + h * 128 + c4);
                *(float4*)&KVs[row * 132 + c4] = v;
            }
        }
        __syncthreads();

        // S = Q K^T (scaled)
        float s[4][4];
#pragma unroll
        for (int i = 0; i < 4; i++)
#pragma unroll
            for (int j = 0; j < 4; j++) s[i][j] = 0.f;
#pragma unroll
        for (int d4 = 0; d4 < 32; d4++) {
            float4 qv[4], kv[4];
#pragma unroll
            for (int i = 0; i < 4; i++) qv[i] = *(const float4*)&Qs[(ty + 16 * i) * 132 + d4 * 4];
#pragma unroll
            for (int j = 0; j < 4; j++) kv[j] = *(const float4*)&KVs[(tx + 16 * j) * 132 + d4 * 4];
#pragma unroll
            for (int i = 0; i < 4; i++)
#pragma unroll
                for (int j = 0; j < 4; j++)
                    s[i][j] += qv[i].x * kv[j].x + qv[i].y * kv[j].y +
                               qv[i].z * kv[j].z + qv[i].w * kv[j].w;
        }

        // Relative-position term + band mask
#pragma unroll
        for (int i = 0; i < 4; i++) {
            int qg = q0 + ty + 16 * i;
            const float* prow = pos_base + (size_t)qg * KV_ + (1023 - qg);
#pragma unroll
            for (int j = 0; j < 4; j++) {
                int mg = m0 + tx + 16 * j;
                if (mg <= qg + TOTMEM_) s[i][j] += prow[mg];
                else                    s[i][j] = -INFINITY;
            }
        }

        // Online softmax
#pragma unroll
        for (int i = 0; i < 4; i++) {
            float mx = fmaxf(fmaxf(s[i][0], s[i][1]), fmaxf(s[i][2], s[i][3]));
            mx = fmaxf(mx, __shfl_xor_sync(0xffffffffu, mx, 1, 16));
            mx = fmaxf(mx, __shfl_xor_sync(0xffffffffu, mx, 2, 16));
            mx = fmaxf(mx, __shfl_xor_sync(0xffffffffu, mx, 4, 16));
            mx = fmaxf(mx, __shfl_xor_sync(0xffffffffu, mx, 8, 16));
            float m_new = fmaxf(m_run[i], mx);
            float corr = __expf(m_run[i] - m_new);
            float p0 = __expf(s[i][0] - m_new);
            float p1 = __expf(s[i][1] - m_new);
            float p2 = __expf(s[i][2] - m_new);
            float p3 = __expf(s[i][3] - m_new);
            float sum = p0 + p1 + p2 + p3;
            sum += __shfl_xor_sync(0xffffffffu, sum, 1, 16);
            sum += __shfl_xor_sync(0xffffffffu, sum, 2, 16);
            sum += __shfl_xor_sync(0xffffffffu, sum, 4, 16);
            sum += __shfl_xor_sync(0xffffffffu, sum, 8, 16);
            l_run[i] = l_run[i] * corr + sum;
            m_run[i] = m_new;
#pragma unroll
            for (int c = 0; c < 8; c++) o[i][c] *= corr;
            int prow_s = (ty + 16 * i) * 65;
            Ps[prow_s + tx + 0]  = p0;
            Ps[prow_s + tx + 16] = p1;
            Ps[prow_s + tx + 32] = p2;
            Ps[prow_s + tx + 48] = p3;
        }
        __syncthreads();

        // Load V tile (reuse KVs)
        {
            int r = tid >> 5;
            int c4 = (tid & 31) * 4;
#pragma unroll
            for (int it = 0; it < 8; it++) {
                int row = r + it * 8;
                float4 v = *(const float4*)(g_v + (size_t)(b * KV_ + m0 + row) * 1024 + h * 128 + c4);
                *(float4*)&KVs[row * 132 + c4] = v;
            }
        }
        __syncthreads();

        // O += P @ V
#pragma unroll 4
        for (int kk = 0; kk < 64; kk++) {
            float pv[4];
#pragma unroll
            for (int i = 0; i < 4; i++) pv[i] = Ps[(ty + 16 * i) * 65 + kk];
#pragma unroll
            for (int c = 0; c < 8; c++) {
                float vv = KVs[kk * 132 + tx + 16 * c];
#pragma unroll
                for (int i = 0; i < 4; i++) o[i][c] = fmaf(pv[i], vv, o[i][c]);
            }
        }
    }

    // Normalize and write out (merged layout: [b, t, h*128 + d])
#pragma unroll
    for (int i = 0; i < 4; i++) {
        int qg = q0 + ty + 16 * i;
        float inv = 1.f / l_run[i];
#pragma unroll
        for (int c = 0; c < 8; c++)
            g_attn[(size_t)(b * T_ + qg) * 1024 + h * 128 + tx + 16 * c] = o[i][c] * inv;
    }
}

// ---------------------------------------------------------------------------
// Tail: new_mem = x (copy), aux_loss = 0
// ---------------------------------------------------------------------------
__global__ void tail_kernel(const float* __restrict__ x, float* __restrict__ out)
{
    const size_t n4 = (size_t)B_ * T_ * E_ / 4;
    float4* dst = (float4*)(out + (size_t)B_ * T_ * E_);
    const float4* src = (const float4*)x;
    size_t i = (size_t)blockIdx.x * blockDim.x + threadIdx.x;
    for (size_t k = i; k < n4; k += (size_t)gridDim.x * blockDim.x) dst[k] = src[k];
    if (i == 0)
        out[(size_t)B_ * T_ * E_ * 2 + (size_t)B_ * CML_ * E_] = 0.f;  // aux_loss
}

// ---------------------------------------------------------------------------
extern "C" void kernel_launch(void* const* d_in, const int* in_sizes, int n_in,
                              void* d_out, int out_size)
{
    (void)in_sizes; (void)n_in;
    const float* x      = (const float*)d_in[0];
    const float* mem    = (const float*)d_in[1];
    const float* cmem   = (const float*)d_in[2];
    const float* pe     = (const float*)d_in[3];
    // d_in[4] = input_mask (all true by construction: jnp.ones) — mask reduces
    // exactly to the causal band already applied in attn_kernel.
    const float* Wq     = (const float*)d_in[5];
    const float* Wkv    = (const float*)d_in[6];
    const float* Wout   = (const float*)d_in[7];
    const float* b_out  = (const float*)d_in[8];
    const float* conv_w = (const float*)d_in[9];
    const float* conv_b = (const float*)d_in[10];

    float* out = (float*)d_out;
    float* out_logits = out;                                   // 4,194,304
    float* out_cmem   = out + (size_t)2 * B_ * T_ * E_;        // at 8,388,608

    cudaFuncSetAttribute(attn_kernel, cudaFuncAttributeMaxDynamicSharedMemorySize,
                         ATTN_SMEM_BYTES);

    // q = x @ Wq                       M=4096 N=1024 K=1024
    sgemm_kernel<MODE_Q><<<dim3(8, 32), 256>>>(x, nullptr, nullptr, Wq, nullptr, nullptr);
    // kv = [cmem;mem;x] @ Wkv          M=9216 N=2048 K=1024
    sgemm_kernel<MODE_KV><<<dim3(16, 72), 256>>>(x, mem, cmem, Wkv, nullptr, nullptr);
    // pos_dots (scaled) = q @ pe^T     per (b,h): M=1024 N=2304 K=128
    sgemm_kernel<MODE_POS><<<dim3(18, 8, 32), 256>>>(nullptr, nullptr, nullptr, pe, nullptr, nullptr);
    // attention
    attn_kernel<<<dim3(16, 32), 256, ATTN_SMEM_BYTES>>>();
    // logits = attn_out @ Wout + b_out M=4096 N=1024 K=1024
    sgemm_kernel<MODE_OUT><<<dim3(8, 32), 256>>>(nullptr, nullptr, nullptr, Wout, b_out, out_logits);

    if (out_size > B_ * T_ * E_) {
        // new_cmem = conv(mem)         M=1024 N=1024 K=4096
        sgemm_kernel<MODE_CMEM><<<dim3(8, 8), 256>>>(nullptr, mem, nullptr, conv_w, conv_b, out_cmem);
        // new_mem = x; aux = 0
        tail_kernel<<<1024, 256>>>(x, out);
    }
}

// round 5
// speedup vs baseline: 1.7306x; 1.7306x over previous
#include <cuda_runtime.h>
#include <cuda_bf16.h>
#include <math.h>
#include <stdint.h>

// Problem constants
#define B_ 4
#define T_ 1024
#define E_ 1024
#define H_ 8
#define DH_ 128
#define KV_ 2304
#define CML_ 256
#define MEML_ 1024
#define TOTMEM_ 1280
#define SCALE_ 0.08838834764831845f

// Scratch (device globals — allocation-free rule)
__device__ float g_q[B_ * T_ * E_];
__device__ float g_k[B_ * KV_ * E_];
__device__ float g_v[B_ * KV_ * E_];
__device__ float g_attn[B_ * T_ * E_];
__device__ float g_pos[(size_t)B_ * H_ * T_ * KV_];   // scaled pos_dots, pre-shift
__device__ float g_cwt[1024 * 4096];                  // conv_w permuted to (o, r*1024+d)

#define MODE_Q 0
#define MODE_KV 1
#define MODE_POS 2
#define MODE_OUT 3
#define MODE_CMEM 4

__device__ __forceinline__ uint32_t tf32r(float f) {
    uint32_t r;
    asm("cvt.rna.tf32.f32 %0, %1;" : "=r"(r) : "f"(f));
    return r;
}

// ---------------------------------------------------------------------------
// tf32 mma.sync GEMM: 128x128x32 block tile, 8 warps, warp tile 32x64
// (2 x m16) x (8 x n8) mma.sync.m16n8k8 per 8-wide k-step
// ---------------------------------------------------------------------------
template <int MODE>
__global__ void __launch_bounds__(256) mma_gemm(
    const float* __restrict__ A0, const float* __restrict__ A1,
    const float* __restrict__ A2, const float* __restrict__ Bmat,
    const float* __restrict__ bias, float* __restrict__ Cout)
{
    constexpr int K    = (MODE == MODE_POS) ? 128 : (MODE == MODE_CMEM ? 4096 : 1024);
    constexpr int LDA  = (MODE == MODE_CMEM) ? 4096 : 1024;
    constexpr int LDBN = (MODE == MODE_KV) ? 2048 : 1024;         // straight modes (K,N)
    constexpr bool BT  = (MODE == MODE_POS || MODE == MODE_CMEM); // B is (N,K): transpose in smem
    constexpr int LDBK = (MODE == MODE_POS) ? 128 : 4096;         // transpose modes
    constexpr int NT   = K / 32;

    __shared__ uint32_t As[32][132];
    __shared__ uint32_t Bs[32][132];

    const int tid = threadIdx.x;
    const int wid = tid >> 5;
    const int lid = tid & 31;
    const int g   = lid >> 2;   // 0..7
    const int tg  = lid & 3;    // 0..3
    const int m0 = blockIdx.y * 128;
    const int n0 = blockIdx.x * 128;
    const int z  = blockIdx.z;
    const int wm = (wid & 3) * 32;
    const int wn = (wid >> 2) * 64;

    // ---- A / B base pointers ----
    const float* Abase;
    const float* Bbase;
    if constexpr (MODE == MODE_Q) {
        Abase = A0 + (size_t)m0 * 1024;
        Bbase = Bmat + n0;
    } else if constexpr (MODE == MODE_KV) {
        int b = m0 / KV_;
        int j = m0 - b * KV_;
        if (j < CML_)              Abase = A2 + (size_t)(b * CML_ + j) * 1024;
        else if (j < CML_ + MEML_) Abase = A1 + (size_t)(b * MEML_ + (j - CML_)) * 1024;
        else                       Abase = A0 + (size_t)(b * T_ + (j - CML_ - MEML_)) * 1024;
        Bbase = Bmat + n0;
    } else if constexpr (MODE == MODE_POS) {
        Abase = g_q + ((size_t)((z >> 3) * T_ + m0)) * 1024 + (z & 7) * 128;
        Bbase = Bmat + ((size_t)((z & 7) * KV_ + n0)) * 128;
    } else if constexpr (MODE == MODE_OUT) {
        Abase = g_attn + (size_t)m0 * 1024;
        Bbase = Bmat + n0;
    } else { // CMEM
        Abase = A1 + (size_t)m0 * 4096;
        Bbase = Bmat + (size_t)n0 * 4096;
    }

    // ---- loader index precompute ----
    const int arow = tid >> 1;              // 0..127
    const int akh  = (tid & 1) * 16;        // 0 or 16
    const float* aPtr = Abase + (size_t)arow * LDA + akh;

    float4 av[4], bv[4];
    auto loadA = [&](int t) {
        const float* p = aPtr + t * 32;
#pragma unroll
        for (int j = 0; j < 4; j++) av[j] = *(const float4*)(p + 4 * j);
    };
    auto loadB = [&](int t) {
        if constexpr (BT) {
            const float* p = Bbase + (size_t)(tid >> 1) * LDBK + (tid & 1) * 16 + t * 32;
#pragma unroll
            for (int j = 0; j < 4; j++) bv[j] = *(const float4*)(p + 4 * j);
        } else {
            const int brow = tid >> 5;           // 0..7 (+8i)
            const int bcol = (tid & 31) * 4;
            const float* p = Bbase + (size_t)(t * 32 + brow) * LDBN + bcol;
#pragma unroll
            for (int j = 0; j < 4; j++) bv[j] = *(const float4*)(p + (size_t)(8 * j) * LDBN);
        }
    };
    auto stsA = [&]() {
#pragma unroll
        for (int j = 0; j < 4; j++) {
            As[akh + 4 * j + 0][arow] = tf32r(av[j].x);
            As[akh + 4 * j + 1][arow] = tf32r(av[j].y);
            As[akh + 4 * j + 2][arow] = tf32r(av[j].z);
            As[akh + 4 * j + 3][arow] = tf32r(av[j].w);
        }
    };
    auto stsB = [&]() {
        if constexpr (BT) {
            const int nrow = tid >> 1;
            const int kh = (tid & 1) * 16;
#pragma unroll
            for (int j = 0; j < 4; j++) {
                Bs[kh + 4 * j + 0][nrow] = tf32r(bv[j].x);
                Bs[kh + 4 * j + 1][nrow] = tf32r(bv[j].y);
                Bs[kh + 4 * j + 2][nrow] = tf32r(bv[j].z);
                Bs[kh + 4 * j + 3][nrow] = tf32r(bv[j].w);
            }
        } else {
            const int brow = tid >> 5;
            const int bcol = (tid & 31) * 4;
#pragma unroll
            for (int j = 0; j < 4; j++) {
                uint32_t* p = &Bs[brow + 8 * j][bcol];
                p[0] = tf32r(bv[j].x); p[1] = tf32r(bv[j].y);
                p[2] = tf32r(bv[j].z); p[3] = tf32r(bv[j].w);
            }
        }
    };

    float c[2][8][4];
#pragma unroll
    for (int mi = 0; mi < 2; mi++)
#pragma unroll
        for (int ni = 0; ni < 8; ni++)
#pragma unroll
            for (int r = 0; r < 4; r++) c[mi][ni][r] = 0.f;

    loadA(0); loadB(0);
    for (int t = 0; t < NT; t++) {
        stsA(); stsB();
        __syncthreads();
        if (t + 1 < NT) { loadA(t + 1); loadB(t + 1); }

#pragma unroll
        for (int kk = 0; kk < 4; kk++) {
            const int kb = kk * 8;
            uint32_t a[2][4];
#pragma unroll
            for (int mi = 0; mi < 2; mi++) {
                a[mi][0] = As[kb + tg][wm + 16 * mi + g];
                a[mi][1] = As[kb + tg][wm + 16 * mi + g + 8];
                a[mi][2] = As[kb + tg + 4][wm + 16 * mi + g];
                a[mi][3] = As[kb + tg + 4][wm + 16 * mi + g + 8];
            }
#pragma unroll
            for (int ni = 0; ni < 8; ni++) {
                uint32_t b0 = Bs[kb + tg][wn + 8 * ni + g];
                uint32_t b1 = Bs[kb + tg + 4][wn + 8 * ni + g];
#pragma unroll
                for (int mi = 0; mi < 2; mi++) {
                    asm volatile(
                        "mma.sync.aligned.m16n8k8.row.col.f32.tf32.tf32.f32 "
                        "{%0,%1,%2,%3}, {%4,%5,%6,%7}, {%8,%9}, {%0,%1,%2,%3};"
                        : "+f"(c[mi][ni][0]), "+f"(c[mi][ni][1]),
                          "+f"(c[mi][ni][2]), "+f"(c[mi][ni][3])
                        : "r"(a[mi][0]), "r"(a[mi][1]), "r"(a[mi][2]), "r"(a[mi][3]),
                          "r"(b0), "r"(b1));
                }
            }
        }
        __syncthreads();
    }

    // ---- epilogue ----
#pragma unroll
    for (int mi = 0; mi < 2; mi++) {
        const int row = m0 + wm + 16 * mi + g;
#pragma unroll
        for (int ni = 0; ni < 8; ni++) {
            const int col = n0 + wn + 8 * ni + 2 * tg;
            float2 lo = make_float2(c[mi][ni][0], c[mi][ni][1]);
            float2 hi = make_float2(c[mi][ni][2], c[mi][ni][3]);
            if constexpr (MODE == MODE_Q) {
                *(float2*)(g_q + (size_t)row * 1024 + col) = lo;
                *(float2*)(g_q + (size_t)(row + 8) * 1024 + col) = hi;
            } else if constexpr (MODE == MODE_KV) {
                float* base = (n0 < 1024) ? g_k : g_v;
                int cc = (n0 < 1024) ? col : col - 1024;
                *(float2*)(base + (size_t)row * 1024 + cc) = lo;
                *(float2*)(base + (size_t)(row + 8) * 1024 + cc) = hi;
            } else if constexpr (MODE == MODE_POS) {
                float* dst = g_pos + (size_t)z * T_ * KV_;
                *(float2*)(dst + (size_t)row * KV_ + col) =
                    make_float2(lo.x * SCALE_, lo.y * SCALE_);
                *(float2*)(dst + (size_t)(row + 8) * KV_ + col) =
                    make_float2(hi.x * SCALE_, hi.y * SCALE_);
            } else { // OUT, CMEM
                float2 bb = *(const float2*)(bias + col);
                *(float2*)(Cout + (size_t)row * 1024 + col) =
                    make_float2(lo.x + bb.x, lo.y + bb.y);
                *(float2*)(Cout + (size_t)(row + 8) * 1024 + col) =
                    make_float2(hi.x + bb.x, hi.y + bb.y);
            }
        }
    }
}

// conv_w (o, d, r) -> (o, r*1024 + d)
__global__ void convw_kernel(const float* __restrict__ in, float* __restrict__ out)
{
    int i = blockIdx.x * 256 + threadIdx.x;
    int o = i >> 12, rem = i & 4095, d = rem >> 2, r = rem & 3;
    out[(size_t)o * 4096 + r * 1024 + d] = in[i];
}

// ---------------------------------------------------------------------------
// Flash-style attention (unchanged from round 1)
// ---------------------------------------------------------------------------
#define ATTN_SMEM_BYTES ((64 * 132 * 2 + 64 * 65) * 4)

__launch_bounds__(256, 2)
__global__ void attn_kernel()
{
    extern __shared__ float sm[];
    float* Qs  = sm;
    float* KVs = sm + 64 * 132;
    float* Ps  = sm + 2 * 64 * 132;

    const int tid = threadIdx.x;
    const int tx = tid & 15;
    const int ty = tid >> 4;
    const int qx = (int)gridDim.x - 1 - (int)blockIdx.x;
    const int q0 = qx * 64;
    const int bh = blockIdx.y;
    const int b = bh >> 3, h = bh & 7;

    {
        int r = tid >> 5;
        int c4 = (tid & 31) * 4;
#pragma unroll
        for (int it = 0; it < 8; it++) {
            int row = r + it * 8;
            float4 v = *(const float4*)(g_q + (size_t)(b * T_ + q0 + row) * 1024 + h * 128 + c4);
            v.x *= SCALE_; v.y *= SCALE_; v.z *= SCALE_; v.w *= SCALE_;
            *(float4*)&Qs[row * 132 + c4] = v;
        }
    }

    float m_run[4], l_run[4], o[4][8];
#pragma unroll
    for (int i = 0; i < 4; i++) {
        m_run[i] = -INFINITY;
        l_run[i] = 0.f;
#pragma unroll
        for (int c = 0; c < 8; c++) o[i][c] = 0.f;
    }

    const int n_tiles = min(KV_ / 64, qx + 21);
    const float* pos_base = g_pos + (size_t)bh * T_ * KV_;

    for (int t = 0; t < n_tiles; t++) {
        const int m0 = t * 64;
        __syncthreads();
        {
            int r = tid >> 5;
            int c4 = (tid & 31) * 4;
#pragma unroll
            for (int it = 0; it < 8; it++) {
                int row = r + it * 8;
                float4 v = *(const float4*)(g_k + (size_t)(b * KV_ + m0 + row) * 1024 + h * 128 + c4);
                *(float4*)&KVs[row * 132 + c4] = v;
            }
        }
        __syncthreads();

        float s[4][4];
#pragma unroll
        for (int i = 0; i < 4; i++)
#pragma unroll
            for (int j = 0; j < 4; j++) s[i][j] = 0.f;
#pragma unroll
        for (int d4 = 0; d4 < 32; d4++) {
            float4 qv[4], kv[4];
#pragma unroll
            for (int i = 0; i < 4; i++) qv[i] = *(const float4*)&Qs[(ty + 16 * i) * 132 + d4 * 4];
#pragma unroll
            for (int j = 0; j < 4; j++) kv[j] = *(const float4*)&KVs[(tx + 16 * j) * 132 + d4 * 4];
#pragma unroll
            for (int i = 0; i < 4; i++)
#pragma unroll
                for (int j = 0; j < 4; j++)
                    s[i][j] += qv[i].x * kv[j].x + qv[i].y * kv[j].y +
                               qv[i].z * kv[j].z + qv[i].w * kv[j].w;
        }

#pragma unroll
        for (int i = 0; i < 4; i++) {
            int qg = q0 + ty + 16 * i;
            const float* prow = pos_base + (size_t)qg * KV_ + (1023 - qg);
#pragma unroll
            for (int j = 0; j < 4; j++) {
                int mg = m0 + tx + 16 * j;
                if (mg <= qg + TOTMEM_) s[i][j] += prow[mg];
                else                    s[i][j] = -INFINITY;
            }
        }

#pragma unroll
        for (int i = 0; i < 4; i++) {
            float mx = fmaxf(fmaxf(s[i][0], s[i][1]), fmaxf(s[i][2], s[i][3]));
            mx = fmaxf(mx, __shfl_xor_sync(0xffffffffu, mx, 1, 16));
            mx = fmaxf(mx, __shfl_xor_sync(0xffffffffu, mx, 2, 16));
            mx = fmaxf(mx, __shfl_xor_sync(0xffffffffu, mx, 4, 16));
            mx = fmaxf(mx, __shfl_xor_sync(0xffffffffu, mx, 8, 16));
            float m_new = fmaxf(m_run[i], mx);
            float corr = __expf(m_run[i] - m_new);
            float p0 = __expf(s[i][0] - m_new);
            float p1 = __expf(s[i][1] - m_new);
            float p2 = __expf(s[i][2] - m_new);
            float p3 = __expf(s[i][3] - m_new);
            float sum = p0 + p1 + p2 + p3;
            sum += __shfl_xor_sync(0xffffffffu, sum, 1, 16);
            sum += __shfl_xor_sync(0xffffffffu, sum, 2, 16);
            sum += __shfl_xor_sync(0xffffffffu, sum, 4, 16);
            sum += __shfl_xor_sync(0xffffffffu, sum, 8, 16);
            l_run[i] = l_run[i] * corr + sum;
            m_run[i] = m_new;
#pragma unroll
            for (int c = 0; c < 8; c++) o[i][c] *= corr;
            int prow_s = (ty + 16 * i) * 65;
            Ps[prow_s + tx + 0]  = p0;
            Ps[prow_s + tx + 16] = p1;
            Ps[prow_s + tx + 32] = p2;
            Ps[prow_s + tx + 48] = p3;
        }
        __syncthreads();

        {
            int r = tid >> 5;
            int c4 = (tid & 31) * 4;
#pragma unroll
            for (int it = 0; it < 8; it++) {
                int row = r + it * 8;
                float4 v = *(const float4*)(g_v + (size_t)(b * KV_ + m0 + row) * 1024 + h * 128 + c4);
                *(float4*)&KVs[row * 132 + c4] = v;
            }
        }
        __syncthreads();

#pragma unroll 4
        for (int kk = 0; kk < 64; kk++) {
            float pv[4];
#pragma unroll
            for (int i = 0; i < 4; i++) pv[i] = Ps[(ty + 16 * i) * 65 + kk];
#pragma unroll
            for (int c = 0; c < 8; c++) {
                float vv = KVs[kk * 132 + tx + 16 * c];
#pragma unroll
                for (int i = 0; i < 4; i++) o[i][c] = fmaf(pv[i], vv, o[i][c]);
            }
        }
    }

#pragma unroll
    for (int i = 0; i < 4; i++) {
        int qg = q0 + ty + 16 * i;
        float inv = 1.f / l_run[i];
#pragma unroll
        for (int c = 0; c < 8; c++)
            g_attn[(size_t)(b * T_ + qg) * 1024 + h * 128 + tx + 16 * c] = o[i][c] * inv;
    }
}

// ---------------------------------------------------------------------------
// Tail: new_mem = x (copy), aux_loss = 0
// ---------------------------------------------------------------------------
__global__ void tail_kernel(const float* __restrict__ x, float* __restrict__ out)
{
    const size_t n4 = (size_t)B_ * T_ * E_ / 4;
    float4* dst = (float4*)(out + (size_t)B_ * T_ * E_);
    const float4* src = (const float4*)x;
    size_t i = (size_t)blockIdx.x * blockDim.x + threadIdx.x;
    for (size_t k = i; k < n4; k += (size_t)gridDim.x * blockDim.x) dst[k] = src[k];
    if (i == 0)
        out[(size_t)B_ * T_ * E_ * 2 + (size_t)B_ * CML_ * E_] = 0.f;
}

// ---------------------------------------------------------------------------
extern "C" void kernel_launch(void* const* d_in, const int* in_sizes, int n_in,
                              void* d_out, int out_size)
{
    (void)in_sizes; (void)n_in;
    const float* x      = (const float*)d_in[0];
    const float* mem    = (const float*)d_in[1];
    const float* cmem   = (const float*)d_in[2];
    const float* pe     = (const float*)d_in[3];
    const float* Wq     = (const float*)d_in[5];
    const float* Wkv    = (const float*)d_in[6];
    const float* Wout   = (const float*)d_in[7];
    const float* b_out  = (const float*)d_in[8];
    const float* conv_w = (const float*)d_in[9];
    const float* conv_b = (const float*)d_in[10];

    float* out = (float*)d_out;
    float* out_logits = out;
    float* out_cmem   = out + (size_t)2 * B_ * T_ * E_;

    float* cwt;
    cudaGetSymbolAddress((void**)&cwt, g_cwt);

    cudaFuncSetAttribute(attn_kernel, cudaFuncAttributeMaxDynamicSharedMemorySize,
                         ATTN_SMEM_BYTES);

    convw_kernel<<<16384, 256>>>(conv_w, cwt);

    // q = x @ Wq                       M=4096 N=1024 K=1024
    mma_gemm<MODE_Q><<<dim3(8, 32), 256>>>(x, nullptr, nullptr, Wq, nullptr, nullptr);
    // kv = [cmem;mem;x] @ Wkv          M=9216 N=2048 K=1024
    mma_gemm<MODE_KV><<<dim3(16, 72), 256>>>(x, mem, cmem, Wkv, nullptr, nullptr);
    // pos_dots (scaled) = q @ pe^T     per (b,h): M=1024 N=2304 K=128
    mma_gemm<MODE_POS><<<dim3(18, 8, 32), 256>>>(nullptr, nullptr, nullptr, pe, nullptr, nullptr);
    // attention
    attn_kernel<<<dim3(16, 32), 256, ATTN_SMEM_BYTES>>>();
    // logits = attn_out @ Wout + b_out M=4096 N=1024 K=1024
    mma_gemm<MODE_OUT><<<dim3(8, 32), 256>>>(nullptr, nullptr, nullptr, Wout, b_out, out_logits);
    // new_cmem = conv(mem)             M=1024 N=1024 K=4096
    mma_gemm<MODE_CMEM><<<dim3(8, 8), 256>>>(nullptr, mem, nullptr, cwt, conv_b, out_cmem);
    // new_mem = x; aux = 0
    tail_kernel<<<1024, 256>>>(x, out);
}